// round 15
// baseline (speedup 1.0000x reference)
#include <cuda_runtime.h>

// Spherical: out = x * |s| — HBM mixed-stream bound (~5.9-6.0 TB/s measured
// ceiling across 14 configurations).
// R15 (final matrix cell): .cs loads + DEFAULT-policy stores. Evict-normal
// dirty lines linger in L2, letting the LTS batch writebacks into longer DRAM
// write bursts (attacks r/w turnaround loss from the scheduling side).
// Otherwise the measured-best shape: 8192 x 256, 4 front-batched LDG.128.

#define THREADS 256
#define V 4
#define SPAN (THREADS * V)   // 1024 float4 = 16KB per block

__global__ void __launch_bounds__(THREADS) spherical_scale_kernel(
    const float4* __restrict__ x,
    const float* __restrict__ s,
    float4* __restrict__ out,
    int n4)
{
    const float scale = fabsf(__ldg(s));

    const int base = blockIdx.x * SPAN + threadIdx.x;
    const int i0 = base;
    const int i1 = base + THREADS;
    const int i2 = base + 2 * THREADS;
    const int i3 = base + 3 * THREADS;

    if (i3 < n4) {
        // 4 independent LDG.128 front-batched (MLP_p1 = 4), streaming reads.
        float4 v0 = __ldcs(&x[i0]);
        float4 v1 = __ldcs(&x[i1]);
        float4 v2 = __ldcs(&x[i2]);
        float4 v3 = __ldcs(&x[i3]);

        v0.x *= scale; v0.y *= scale; v0.z *= scale; v0.w *= scale;
        v1.x *= scale; v1.y *= scale; v1.z *= scale; v1.w *= scale;
        v2.x *= scale; v2.y *= scale; v2.z *= scale; v2.w *= scale;
        v3.x *= scale; v3.y *= scale; v3.z *= scale; v3.w *= scale;

        // Default-policy stores: dirty lines buffer in L2, writebacks batch.
        out[i0] = v0;
        out[i1] = v1;
        out[i2] = v2;
        out[i3] = v3;
    } else {
        #pragma unroll
        for (int k = 0; k < V; k++) {
            int i = base + k * THREADS;
            if (i < n4) {
                float4 v = __ldcs(&x[i]);
                v.x *= scale; v.y *= scale; v.z *= scale; v.w *= scale;
                out[i] = v;
            }
        }
    }
}

// Scalar remainder for n not divisible by 4 (unused at 8192x4096).
__global__ void __launch_bounds__(256) spherical_scale_tail(
    const float* __restrict__ x,
    const float* __restrict__ s,
    float* __restrict__ out,
    int start, int n)
{
    const float scale = fabsf(__ldg(s));
    int i = start + blockIdx.x * blockDim.x + threadIdx.x;
    if (i < n) out[i] = x[i] * scale;
}

extern "C" void kernel_launch(void* const* d_in, const int* in_sizes, int n_in,
                              void* d_out, int out_size)
{
    const float4* x = (const float4*)d_in[0];
    const float*  s = (const float*)d_in[1];
    float4* out = (float4*)d_out;

    const int n  = in_sizes[0];                 // 33554432
    const int n4 = n / 4;                       // 8388608
    const int blocks = (n4 + SPAN - 1) / SPAN;  // 8192

    spherical_scale_kernel<<<blocks, THREADS>>>(x, s, out, n4);

    const int covered = n4 * 4;
    if (covered < n) {
        const int rem = n - covered;
        spherical_scale_tail<<<(rem + 255) / 256, 256>>>(
            (const float*)d_in[0], s, (float*)d_out, covered, n);
    }
}

// round 16
// speedup vs baseline: 1.0287x; 1.0287x over previous
#include <cuda_runtime.h>

// Spherical: out = x * |s|  (reference GEMM against |s|*I == elementwise scale).
//
// FINAL — converged at the hardware roofline after 15 measured rounds.
// Pure HBM stream: 268 MB logical traffic/call. Every controllable lever was
// sampled (MLP 1/4/8, occ 29-84%, block 128/256, software pipelining,
// persistent single-wave grid, 256-bit v8 ld/st, L2::256B prefetch, all four
// L2 residency policy cells, TMA 16KB bulk streaming) and ALL land at 72-75%
// of DRAM spec: ~5.9-6.0 TB/s combined read+write is the B300 mixed-stream
// ceiling, path-independent (consistent with B300_MICROARCH's LTS-cap data).
//
// This is the measured-fastest configuration, reproduced at the best harness
// time on four independent rounds: 8192 blocks x 256 threads, 4 front-batched
// LDG.128 per thread (MLP_p1=4, 64B/thread), streaming .cs loads and stores,
// 26 registers, ~79% occupancy.

#define THREADS 256
#define V 4
#define SPAN (THREADS * V)   // 1024 float4 = 16KB per block

__global__ void __launch_bounds__(THREADS) spherical_scale_kernel(
    const float4* __restrict__ x,
    const float* __restrict__ s,
    float4* __restrict__ out,
    int n4)
{
    const float scale = fabsf(__ldg(s));

    const int base = blockIdx.x * SPAN + threadIdx.x;
    const int i0 = base;
    const int i1 = base + THREADS;
    const int i2 = base + 2 * THREADS;
    const int i3 = base + 3 * THREADS;

    if (i3 < n4) {
        // Fast path: 4 independent LDG.128 front-batched, fully coalesced.
        float4 v0 = __ldcs(&x[i0]);
        float4 v1 = __ldcs(&x[i1]);
        float4 v2 = __ldcs(&x[i2]);
        float4 v3 = __ldcs(&x[i3]);

        v0.x *= scale; v0.y *= scale; v0.z *= scale; v0.w *= scale;
        v1.x *= scale; v1.y *= scale; v1.z *= scale; v1.w *= scale;
        v2.x *= scale; v2.y *= scale; v2.z *= scale; v2.w *= scale;
        v3.x *= scale; v3.y *= scale; v3.z *= scale; v3.w *= scale;

        __stcs(&out[i0], v0);
        __stcs(&out[i1], v1);
        __stcs(&out[i2], v2);
        __stcs(&out[i3], v3);
    } else {
        #pragma unroll
        for (int k = 0; k < V; k++) {
            int i = base + k * THREADS;
            if (i < n4) {
                float4 v = __ldcs(&x[i]);
                v.x *= scale; v.y *= scale; v.z *= scale; v.w *= scale;
                __stcs(&out[i], v);
            }
        }
    }
}

// Scalar remainder for n not divisible by 4 (unused at 8192x4096).
__global__ void __launch_bounds__(256) spherical_scale_tail(
    const float* __restrict__ x,
    const float* __restrict__ s,
    float* __restrict__ out,
    int start, int n)
{
    const float scale = fabsf(__ldg(s));
    int i = start + blockIdx.x * blockDim.x + threadIdx.x;
    if (i < n) out[i] = x[i] * scale;
}

extern "C" void kernel_launch(void* const* d_in, const int* in_sizes, int n_in,
                              void* d_out, int out_size)
{
    const float4* x = (const float4*)d_in[0];
    const float*  s = (const float*)d_in[1];
    float4* out = (float4*)d_out;

    const int n  = in_sizes[0];                 // 33554432
    const int n4 = n / 4;                       // 8388608
    const int blocks = (n4 + SPAN - 1) / SPAN;  // 8192

    spherical_scale_kernel<<<blocks, THREADS>>>(x, s, out, n4);

    const int covered = n4 * 4;
    if (covered < n) {
        const int rem = n - covered;
        spherical_scale_tail<<<(rem + 255) / 256, 256>>>(
            (const float*)d_in[0], s, (float*)d_out, covered, n);
    }
}